// round 11
// baseline (speedup 1.0000x reference)
#include <cuda_runtime.h>
#include <cuda_fp16.h>
#include <cstdint>

// ---------------------------------------------------------------------------
// SO3Linear (L=3, B=1024, C=256) via pure-fp16 mma.sync GEMM (1 term).
//
//  K1 wsplit+setup  : W[w][ci][co] fp32 -> Wt[w][co][ci] fp16; block(0,0,0)
//                     also builds range tables from seg1/seg2.
//  K2 build_inter   : inter[g][b][ci] fp32 -> A[g][b][ci] fp16 (g-split x8)
//  K3 so3_mma       : per CTA (64 b-rows, 128 co, order M): fp32 accum of
//                     sum_g A@W. 4 warps (2m x 2n, warp tile 32x64), KT=64,
//                     3-stage cp.async ring (1 sync/stage), 3 CTAs/SM.
//  Quantization err: A + W fp16 rounding => ~2.9e-4 << 1e-3.
// ---------------------------------------------------------------------------

#define NORD     16
#define CI       256
#define CO       256
#define G_MAX    156
#define NNZ_MAX  512
#define NW_MAX   40
#define B_MAX    1024

// ---- device scratch ----
__device__ __half g_af[(size_t)G_MAX * B_MAX * CI];   // A fp16
__device__ __half g_wf[(size_t)NW_MAX * CO * CI];     // W fp16 (transposed)
__device__ int g_gs[G_MAX + 1];
__device__ int g_mg[NORD + 1];

// heavy-orders-first schedule (groups/M: l=2 ->11, l=3 ->10, l=1 ->9, l=0 ->4)
__constant__ int c_morder[NORD] = {4,5,6,7,8, 9,10,11,12,13,14,15, 1,2,3, 0};

#define SWZ(o) ((o) ^ (((o) >> 3) & 0x70))

__device__ __forceinline__ uint32_t smem_u32(const void* p) {
    uint32_t a;
    asm("{ .reg .u64 t; cvta.to.shared.u64 t, %1; cvt.u32.u64 %0, t; }" : "=r"(a) : "l"(p));
    return a;
}
__device__ __forceinline__ void cp16(uint32_t dst, const void* src) {
    asm volatile("cp.async.cg.shared.global [%0], [%1], 16;" :: "r"(dst), "l"(src) : "memory");
}
#define CP_COMMIT()  asm volatile("cp.async.commit_group;" ::: "memory")
#define CP_WAIT(N)   asm volatile("cp.async.wait_group %0;" :: "n"(N) : "memory")

__device__ __forceinline__ void ldsm4(uint32_t r[4], uint32_t addr) {
    asm volatile("ldmatrix.sync.aligned.m8n8.x4.shared.b16 {%0,%1,%2,%3}, [%4];"
                 : "=r"(r[0]), "=r"(r[1]), "=r"(r[2]), "=r"(r[3]) : "r"(addr));
}
__device__ __forceinline__ void mma16816(float c[4], const uint32_t a[4],
                                         uint32_t b0, uint32_t b1) {
    asm volatile(
        "mma.sync.aligned.m16n8k16.row.col.f32.f16.f16.f32 "
        "{%0,%1,%2,%3}, {%4,%5,%6,%7}, {%8,%9}, {%0,%1,%2,%3};"
        : "+f"(c[0]), "+f"(c[1]), "+f"(c[2]), "+f"(c[3])
        : "r"(a[0]), "r"(a[1]), "r"(a[2]), "r"(a[3]), "r"(b0), "r"(b1));
}

// ---------------------------------------------------------------------------
// K1: transpose weights to fp16 + (block 0) build range tables.
// ---------------------------------------------------------------------------
__global__ __launch_bounds__(256) void wsplit(const float* __restrict__ weight,
                                              const int* __restrict__ seg1,
                                              const int* __restrict__ seg2,
                                              int nnz, int G) {
    __shared__ float tile[32][33];
    const int w  = blockIdx.z;
    const int bx = blockIdx.x;   // co block
    const int by = blockIdx.y;   // ci block
    const int tx = threadIdx.x & 31;
    const int ty = threadIdx.x >> 5;

    if (bx == 0 && by == 0 && w == 0) {
        int tid = threadIdx.x;
        for (int i = tid; i < nnz; i += blockDim.x) {
            if (i == 0) g_gs[seg1[0]] = 0;
            else if (seg1[i] != seg1[i - 1]) g_gs[seg1[i]] = i;
        }
        for (int i = tid; i < G; i += blockDim.x) {
            if (i == 0) g_mg[seg2[0]] = 0;
            else if (seg2[i] != seg2[i - 1]) g_mg[seg2[i]] = i;
        }
        if (tid == 0) { g_gs[G] = nnz; g_mg[NORD] = G; }
    }

    const float* in = weight + (size_t)w * CI * CO;
#pragma unroll
    for (int j = 0; j < 4; ++j) {
        int r = ty + 8 * j;
        tile[r][tx] = in[(size_t)(by * 32 + r) * CO + bx * 32 + tx];
    }
    __syncthreads();
#pragma unroll
    for (int j = 0; j < 4; ++j) {
        int r = ty + 8 * j;
        float v = tile[tx][r];
        size_t o = ((size_t)w * CO + (bx * 32 + r)) * CI + by * 32 + tx;
        g_wf[o] = __float2half(v);
    }
}

// ---------------------------------------------------------------------------
// K2: build inter (vectorized, g-split x8). Block = 4 b; thread owns 4 ci.
// ---------------------------------------------------------------------------
__global__ __launch_bounds__(256) void build_inter(
    const float* __restrict__ x,
    const float* __restrict__ sh,
    const float* __restrict__ CG,
    const int* __restrict__ M1,
    const int* __restrict__ M2,
    int nnz, int G, int Bn) {

    __shared__ float coefs4[4][NNZ_MAX];
    __shared__ int   m1s[NNZ_MAX];
    __shared__ int   gs_s[G_MAX + 1];

    const int b_base = blockIdx.x * 4;
    const int q      = blockIdx.y;
    const int tid    = threadIdx.x;
    const int bsub   = tid >> 6;
    const int c4     = (tid & 63) * 4;

    const int gq0 = (G * q) >> 3;
    const int gq1 = (G * (q + 1)) >> 3;

    for (int i = tid; i <= G; i += 256) gs_s[i] = g_gs[i];
    __syncthreads();
    const int n0 = gs_s[gq0];
    const int n1 = gs_s[gq1];

    for (int i = n0 + tid; i < n1; i += 256) m1s[i] = M1[i] * CI;
#pragma unroll
    for (int bb = 0; bb < 4; ++bb) {
        const float* shb = sh + (size_t)(b_base + bb) * NORD;
        for (int i = n0 + tid; i < n1; i += 256)
            coefs4[bb][i] = CG[i] * shb[M2[i]];
    }
    __syncthreads();

    const int b = b_base + bsub;
    const float* xb = x + (size_t)b * NORD * CI + c4;
    const float* cf = coefs4[bsub];

    for (int g = gq0; g < gq1; ++g) {
        float ax = 0.f, ay = 0.f, az = 0.f, aw = 0.f;
        const int e = gs_s[g + 1];
        for (int idx = gs_s[g]; idx < e; ++idx) {
            const float c = cf[idx];
            const float4 xv = *reinterpret_cast<const float4*>(xb + m1s[idx]);
            ax = fmaf(c, xv.x, ax);
            ay = fmaf(c, xv.y, ay);
            az = fmaf(c, xv.z, az);
            aw = fmaf(c, xv.w, aw);
        }
        __half2 h01 = __floats2half2_rn(ax, ay);
        __half2 h23 = __floats2half2_rn(az, aw);
        size_t o = ((size_t)g * Bn + b) * CI + c4;
        *reinterpret_cast<uint2*>(g_af + o) =
            make_uint2(*(uint32_t*)&h01, *(uint32_t*)&h23);
    }
}

// ---------------------------------------------------------------------------
// K3: mma.sync GEMM. Grid (Bn/64, CO/128, NORD), 128 threads (4 warps:
// 2m x 2n, warp tile 32x64). Block tile 64(b) x 128(co), KT=64.
// Stage 24KB: A 8K | W 16K. 3-stage ring, 1 sync/stage -> 73KB, 3 CTAs/SM.
// ---------------------------------------------------------------------------
#define KT          64
#define OFF_W       8192
#define STAGE_BYTES 24576
#define NSTAGE      3
#define SMEM_DYN    (NSTAGE * STAGE_BYTES + 1024)

__device__ __forceinline__ void load_stage(uint32_t st,
                                           const char* gA, const char* gW,
                                           int tid) {
    // A: 64 rows x 8 chunks of 16B (row = 128B = 64 fp16 of this k-slab)
#pragma unroll
    for (int i = 0; i < 4; ++i) {
        int idx = tid + i * 128;
        int r = idx >> 3, c = idx & 7;
        cp16(st + SWZ(r * 128 + c * 16), gA + (size_t)r * (CI * 2) + c * 16);
    }
    // W: 128 rows x 8 chunks
#pragma unroll
    for (int i = 0; i < 8; ++i) {
        int idx = tid + i * 128;
        int r = idx >> 3, c = idx & 7;
        cp16(st + OFF_W + SWZ(r * 128 + c * 16), gW + (size_t)r * (CI * 2) + c * 16);
    }
}

__global__ __launch_bounds__(128, 3) void so3_mma(
    const int* __restrict__ l_ind,
    float* __restrict__ out,
    int Bn) {

    extern __shared__ char smem[];
    const uint32_t sb   = smem_u32(smem);
    const uint32_t base = (sb + 1023) & ~1023u;

    const int tid  = threadIdx.x;
    const int wid  = tid >> 5;
    const int lane = tid & 31;
    const int wm   = wid & 1;          // 2 m-warps (32 rows each)
    const int wn   = wid >> 1;         // 2 n-warps (64 cols each)

    const int b0  = blockIdx.x * 64;
    const int cob = blockIdx.y * 128;
    const int M   = c_morder[blockIdx.z];
    const int gbeg = g_mg[M];
    const int gend = g_mg[M + 1];
    const int T = (gend - gbeg) * (CI / KT);   // k-tiles (4 per group)

    float acc[2][8][4];
#pragma unroll
    for (int i = 0; i < 2; ++i)
#pragma unroll
        for (int j = 0; j < 8; ++j)
#pragma unroll
            for (int q = 0; q < 4; ++q) acc[i][j][q] = 0.f;

    auto srcA = [&](int t) -> const char* {
        int g = gbeg + (t >> 2), kc = t & 3;
        return (const char*)g_af + (((size_t)g * Bn + b0) * CI + kc * KT) * 2;
    };
    auto srcW = [&](int t) -> const char* {
        int g = gbeg + (t >> 2), kc = t & 3;
        int w = __ldg(l_ind + g);
        return (const char*)g_wf + (((size_t)w * CO + cob) * CI + kc * KT) * 2;
    };

    // prologue: 2 stages in flight (T >= 16 always)
    load_stage(base,               srcA(0), srcW(0), tid);
    CP_COMMIT();
    load_stage(base + STAGE_BYTES, srcA(1), srcW(1), tid);
    CP_COMMIT();

    // ldmatrix lane addressing
    const int arow = wm * 32 + (lane & 15);
    const int acol = (lane >> 4) * 16;
    const int wrow = wn * 64 + (lane & 7) + ((lane >> 4) << 3);
    const int wcol = ((lane >> 3) & 1) * 16;

    int s_cur = 0;
    for (int t = 0; t < T; ++t) {
        CP_WAIT(1);                 // tile t's group complete
        __syncthreads();            // all warps done with tile t-1's stage

        if (t + 2 < T) {
            int s_nxt = s_cur + 2; if (s_nxt >= NSTAGE) s_nxt -= NSTAGE;
            load_stage(base + (uint32_t)s_nxt * STAGE_BYTES,
                       srcA(t + 2), srcW(t + 2), tid);
        }
        CP_COMMIT();                // keep group accounting aligned

        const uint32_t st = base + (uint32_t)s_cur * STAGE_BYTES;
        if (++s_cur == NSTAGE) s_cur = 0;

#pragma unroll
        for (int ks = 0; ks < KT / 16; ++ks) {
            const int kb = ks * 32;                // 16 fp16 = 32B
            uint32_t af[2][4];
#pragma unroll
            for (int mi = 0; mi < 2; ++mi) {
                uint32_t ad = st + SWZ((arow + mi * 16) * 128 + kb + acol);
                ldsm4(af[mi], ad);
            }
#pragma unroll
            for (int j = 0; j < 4; ++j) {          // four n16 chunks (64 cols)
                uint32_t wf[4];
                uint32_t wd = st + OFF_W + SWZ((wrow + j * 16) * 128 + kb + wcol);
                ldsm4(wf, wd);
#pragma unroll
                for (int mi = 0; mi < 2; ++mi)
#pragma unroll
                    for (int s = 0; s < 2; ++s)
                        mma16816(acc[mi][j * 2 + s], af[mi], wf[s * 2], wf[s * 2 + 1]);
            }
        }
    }

    // epilogue: out[b0+.., M, cob+..] written exactly once
#pragma unroll
    for (int mi = 0; mi < 2; ++mi) {
        const int m0 = b0 + wm * 32 + mi * 16 + (lane >> 2);
#pragma unroll
        for (int j = 0; j < 8; ++j) {
            const int n = cob + wn * 64 + j * 8 + (lane & 3) * 2;
            float* p0 = out + ((size_t)m0 * NORD + M) * CO + n;
            float* p1 = out + ((size_t)(m0 + 8) * NORD + M) * CO + n;
            *(float2*)p0 = make_float2(acc[mi][j][0], acc[mi][j][1]);
            *(float2*)p1 = make_float2(acc[mi][j][2], acc[mi][j][3]);
        }
    }
}

// ---------------------------------------------------------------------------
// Inputs: x, sh, weight, CG_vals, M1, M2, seg1, l_ind, seg2, num_orders_out
// ---------------------------------------------------------------------------
extern "C" void kernel_launch(void* const* d_in, const int* in_sizes, int n_in,
                              void* d_out, int out_size) {
    const float* x      = (const float*)d_in[0];
    const float* sh     = (const float*)d_in[1];
    const float* weight = (const float*)d_in[2];
    const float* CG     = (const float*)d_in[3];
    const int*   M1     = (const int*)d_in[4];
    const int*   M2     = (const int*)d_in[5];
    const int*   seg1   = (const int*)d_in[6];
    const int*   l_ind  = (const int*)d_in[7];
    const int*   seg2   = (const int*)d_in[8];
    float*       out    = (float*)d_out;

    const int nnz = in_sizes[4];
    const int G   = in_sizes[7];
    const int Bn  = in_sizes[1] / NORD;
    const int n_w = in_sizes[2] / (CI * CO);

    static bool attr_set = false;
    if (!attr_set) {
        cudaFuncSetAttribute(so3_mma, cudaFuncAttributeMaxDynamicSharedMemorySize, SMEM_DYN);
        attr_set = true;
    }

    {
        dim3 grid(CO / 32, CI / 32, n_w);
        wsplit<<<grid, 256>>>(weight, seg1, seg2, nnz, G);
    }
    {
        dim3 grid(Bn / 4, 8);
        build_inter<<<grid, 256>>>(x, sh, CG, M1, M2, nnz, G, Bn);
    }
    {
        dim3 grid(Bn / 64, CO / 128, NORD);
        so3_mma<<<grid, 128, SMEM_DYN>>>(l_ind, out, Bn);
    }
}